// round 3
// baseline (speedup 1.0000x reference)
#include <cuda_runtime.h>

// HMM forward: alpha_t = (alpha_{t-1} @ A) * B[:, obs_t],  out = sum(alpha_{T-1})
// Persistent kernel, A (16 MB) register-resident (128 blocks x 256 thr x 128 regs).
// R3: fully decoupled warps — each warp polls its own half's flags, loads alpha
// straight to registers (no SMEM staging), ONE bar.sync per step, parity-buffered
// partials, single release publish per block.

namespace {
constexpr int GRID = 128;
constexpr int NT   = 256;
constexpr int S    = 2048;
constexpr int V    = 32768;
constexpr int T    = 4096;
constexpr int NCOL = S / GRID;  // 16 output columns per block
}

__device__ float    g_alpha[2][S];
__device__ unsigned g_flag[2][GRID];

__device__ __forceinline__ unsigned ld_rlx(const unsigned* p) {
    unsigned v;
    asm volatile("ld.relaxed.gpu.global.b32 %0, [%1];" : "=r"(v) : "l"(p) : "memory");
    return v;
}
__device__ __forceinline__ void fence_acq() {
    asm volatile("fence.acq_rel.gpu;" ::: "memory");
}
__device__ __forceinline__ void st_rel(unsigned* p, unsigned v) {
    asm volatile("st.release.gpu.global.b32 [%0], %1;" :: "l"(p), "r"(v) : "memory");
}

__global__ void __launch_bounds__(NT, 1) hmm_forward_kernel(
    const int*   __restrict__ obs,
    const float* __restrict__ A,
    const float* __restrict__ B,
    const float* __restrict__ pi,
    float*       __restrict__ out)
{
    __shared__ float red[2][2][NCOL];   // [step parity][row group][col] partials
    __shared__ float bjs[2][NCOL];      // [step parity] emission factors

    const int tid  = threadIdx.x;
    const int blk  = blockIdx.x;
    const int w    = tid >> 5;
    const int lane = tid & 31;
    const int cg   = w & 3;               // column group 0..3 (4 cols each)
    const int rg   = w >> 2;              // row group 0..1 (1024 rows each)
    const int jb   = blk * NCOL + cg * 4; // first of this warp's 4 columns

    // ---- Load A tile into registers (one time) ----
    // Thread covers rows rg*1024 + 4*lane + 128*k + rr (k<8, rr<4), cols jb..jb+3.
    float4 areg[8][4];
#pragma unroll
    for (int k = 0; k < 8; k++) {
#pragma unroll
        for (int rr = 0; rr < 4; rr++) {
            int row = rg * 1024 + 4 * lane + 128 * k + rr;
            areg[k][rr] = *reinterpret_cast<const float4*>(&A[(size_t)row * S + jb]);
        }
    }

    // ---- Init: alpha0 = pi * B[:, obs[0]]; publish with tag 1 ----
    if (tid < NCOL) {
        int   j  = blk * NCOL + tid;
        int   o0 = __ldg(&obs[0]);
        float v  = pi[j] * __ldg(&B[(size_t)j * V + o0]);
        __stcg(&g_alpha[0][j], v);
        if (blk == 0 && tid == 0) *out = 0.0f;
    }
    __syncthreads();
    if (tid == 0) st_rel(&g_flag[0][blk], 1u);

    for (int s = 1; s < T; s++) {
        const int p  = (s - 1) & 1;       // buffer holding alpha_{s-1}
        const int sp = s & 1;             // this step's parity

        // Emission prefetch (independent of alpha).
        if (tid < NCOL) {
            int o = __ldg(&obs[s]);
            bjs[sp][tid] = __ldg(&B[(size_t)(blk * NCOL + tid) * V + o]);
        }

        // Per-warp poll: this warp's row half = 64 producers (2 flag words/lane).
        {
            const unsigned* fl = &g_flag[p][rg * 64];
            const unsigned tag = (unsigned)s;
            for (;;) {
                unsigned a = ld_rlx(fl + lane);
                unsigned b = ld_rlx(fl + lane + 32);
                if (__all_sync(0xffffffffu, (a == tag) & (b == tag))) break;
            }
            fence_acq();
        }

        // Alpha straight to registers: 8 x LDG.128 in flight.
        float4 av[8];
        const float4* ga4 = reinterpret_cast<const float4*>(g_alpha[p]) + rg * 256 + lane;
#pragma unroll
        for (int k = 0; k < 8; k++) av[k] = __ldcg(ga4 + 32 * k);

        // ---- Matvec slice: 128 FMAs per thread, A from registers ----
        float acc0 = 0.f, acc1 = 0.f, acc2 = 0.f, acc3 = 0.f;
#pragma unroll
        for (int k = 0; k < 8; k++) {
            float4 a0 = areg[k][0], a1 = areg[k][1], a2 = areg[k][2], a3 = areg[k][3];
            acc0 = fmaf(av[k].x, a0.x, acc0);
            acc1 = fmaf(av[k].x, a0.y, acc1);
            acc2 = fmaf(av[k].x, a0.z, acc2);
            acc3 = fmaf(av[k].x, a0.w, acc3);
            acc0 = fmaf(av[k].y, a1.x, acc0);
            acc1 = fmaf(av[k].y, a1.y, acc1);
            acc2 = fmaf(av[k].y, a1.z, acc2);
            acc3 = fmaf(av[k].y, a1.w, acc3);
            acc0 = fmaf(av[k].z, a2.x, acc0);
            acc1 = fmaf(av[k].z, a2.y, acc1);
            acc2 = fmaf(av[k].z, a2.z, acc2);
            acc3 = fmaf(av[k].z, a2.w, acc3);
            acc0 = fmaf(av[k].w, a3.x, acc0);
            acc1 = fmaf(av[k].w, a3.y, acc1);
            acc2 = fmaf(av[k].w, a3.z, acc2);
            acc3 = fmaf(av[k].w, a3.w, acc3);
        }

        // Warp reduce (rows split across lanes).
#pragma unroll
        for (int off = 16; off > 0; off >>= 1) {
            acc0 += __shfl_xor_sync(0xffffffffu, acc0, off);
            acc1 += __shfl_xor_sync(0xffffffffu, acc1, off);
            acc2 += __shfl_xor_sync(0xffffffffu, acc2, off);
            acc3 += __shfl_xor_sync(0xffffffffu, acc3, off);
        }
        if (lane == 0) {
            red[sp][rg][cg * 4 + 0] = acc0;
            red[sp][rg][cg * 4 + 1] = acc1;
            red[sp][rg][cg * 4 + 2] = acc2;
            red[sp][rg][cg * 4 + 3] = acc3;
        }
        __syncthreads();   // the ONLY block-wide sync per step

        // Single-thread epilogue: finalize 16 outputs, publish with one release.
        if (tid == 0) {
            const float4* r0 = reinterpret_cast<const float4*>(red[sp][0]);
            const float4* r1 = reinterpret_cast<const float4*>(red[sp][1]);
            const float4* bb = reinterpret_cast<const float4*>(bjs[sp]);
            float4 v[4];
#pragma unroll
            for (int q = 0; q < 4; q++) {
                float4 a = r0[q], b = r1[q], c = bb[q];
                v[q].x = (a.x + b.x) * c.x;
                v[q].y = (a.y + b.y) * c.y;
                v[q].z = (a.z + b.z) * c.z;
                v[q].w = (a.w + b.w) * c.w;
            }
            if (s == T - 1) {
                float vs = 0.f;
#pragma unroll
                for (int q = 0; q < 4; q++) vs += v[q].x + v[q].y + v[q].z + v[q].w;
                atomicAdd(out, vs);
            } else {
                float4* dst = reinterpret_cast<float4*>(&g_alpha[sp][blk * NCOL]);
#pragma unroll
                for (int q = 0; q < 4; q++) __stcg(&dst[q], v[q]);
                st_rel(&g_flag[sp][blk], (unsigned)(s + 1));
            }
        }
        // No trailing barrier: red/bjs are parity double-buffered, and a warp
        // can only reach the NEXT write to this parity slot after passing the
        // next step's barrier, which follows tid0's reads here.
    }
}

extern "C" void kernel_launch(void* const* d_in, const int* in_sizes, int n_in,
                              void* d_out, int out_size) {
    const int*   obs = (const int*)d_in[0];
    const float* A   = (const float*)d_in[1];
    const float* B   = (const float*)d_in[2];
    const float* pi  = (const float*)d_in[3];
    float*       out = (float*)d_out;
    (void)in_sizes; (void)n_in; (void)out_size;

    hmm_forward_kernel<<<GRID, NT>>>(obs, A, B, pi, out);
}

// round 4
// speedup vs baseline: 1.4526x; 1.4526x over previous
#include <cuda_runtime.h>

// HMM forward: alpha_t = (alpha_{t-1} @ A) * B[:, obs_t],  out = sum(alpha_{T-1})
// Persistent kernel, A (16 MB) register-resident (128 blocks x 256 thr x 128 regs).
// R4: one poll warp per block, ONE vectorized volatile LDG per poll iteration
// (all 128 flags in 512B), relaxed poll + single fence, alpha direct to regs,
// one bar.sync per step, epilogue on warp 7 (decoupled from the poller).

namespace {
constexpr int GRID = 128;
constexpr int NT   = 256;
constexpr int S    = 2048;
constexpr int V    = 32768;
constexpr int T    = 4096;
constexpr int NCOL = S / GRID;  // 16 output columns per block
}

__device__ float g_alpha[2][S];
__device__ uint4 g_flag4[2][GRID / 4];   // 128 tag words per parity, 16B-aligned

__device__ __forceinline__ uint4 ld_vol4(const uint4* p) {
    uint4 v;
    asm volatile("ld.volatile.global.v4.u32 {%0,%1,%2,%3}, [%4];"
                 : "=r"(v.x), "=r"(v.y), "=r"(v.z), "=r"(v.w) : "l"(p) : "memory");
    return v;
}
__device__ __forceinline__ void fence_acq() {
    asm volatile("fence.acq_rel.gpu;" ::: "memory");
}
__device__ __forceinline__ void st_rel(unsigned* p, unsigned v) {
    asm volatile("st.release.gpu.global.b32 [%0], %1;" :: "l"(p), "r"(v) : "memory");
}

__global__ void __launch_bounds__(NT, 1) hmm_forward_kernel(
    const int*   __restrict__ obs,
    const float* __restrict__ A,
    const float* __restrict__ B,
    const float* __restrict__ pi,
    float*       __restrict__ out)
{
    __shared__ float red[2][2][NCOL];   // [step parity][row group][col] partials
    __shared__ float bjs[2][NCOL];      // [step parity] emission factors

    const int tid  = threadIdx.x;
    const int blk  = blockIdx.x;
    const int w    = tid >> 5;
    const int lane = tid & 31;
    const int cg   = w & 3;               // column group 0..3 (4 cols each)
    const int rg   = w >> 2;              // row group 0..1 (1024 rows each)
    const int jb   = blk * NCOL + cg * 4; // first of this warp's 4 columns

    // ---- Load A tile into registers (one time) ----
    // Thread covers rows rg*1024 + 4*lane + 128*k + rr (k<8, rr<4), cols jb..jb+3.
    float4 areg[8][4];
#pragma unroll
    for (int k = 0; k < 8; k++) {
#pragma unroll
        for (int rr = 0; rr < 4; rr++) {
            int row = rg * 1024 + 4 * lane + 128 * k + rr;
            areg[k][rr] = *reinterpret_cast<const float4*>(&A[(size_t)row * S + jb]);
        }
    }

    // ---- Init: alpha0 = pi * B[:, obs[0]]; publish with tag 1 ----
    if (tid < NCOL) {
        int   j  = blk * NCOL + tid;
        int   o0 = __ldg(&obs[0]);
        float v  = pi[j] * __ldg(&B[(size_t)j * V + o0]);
        __stcg(&g_alpha[0][j], v);
        if (blk == 0 && tid == 0) __stcg(out, 0.0f);
    }
    __syncthreads();
    if (tid == 0) st_rel(&reinterpret_cast<unsigned*>(g_flag4[0])[blk], 1u);

    for (int s = 1; s < T; s++) {
        const int p  = (s - 1) & 1;       // buffer holding alpha_{s-1}
        const int sp = s & 1;             // this step's parity

        // Emission prefetch (independent of alpha).
        if (tid >= 224 && tid < 224 + NCOL) {
            int t = tid - 224;
            int o = __ldg(&obs[s]);
            bjs[sp][t] = __ldg(&B[(size_t)(blk * NCOL + t) * V + o]);
        }

        // Warp 0: poll all 128 tags with ONE volatile v4 load per iteration.
        if (w == 0) {
            const uint4* fl = &g_flag4[p][lane];
            const unsigned tag = (unsigned)s;
            for (;;) {
                uint4 f = ld_vol4(fl);
                bool ok = (f.x == tag) & (f.y == tag) & (f.z == tag) & (f.w == tag);
                if (__all_sync(0xffffffffu, ok)) break;
            }
            fence_acq();
        }
        __syncthreads();   // releases all warps once flags are in

        // Alpha straight to registers: 8 x LDG.128 in flight.
        float4 av[8];
        const float4* ga4 = reinterpret_cast<const float4*>(g_alpha[p]) + rg * 256 + lane;
#pragma unroll
        for (int k = 0; k < 8; k++) av[k] = __ldcg(ga4 + 32 * k);

        // ---- Matvec slice: 128 FMAs per thread, A from registers ----
        float acc0 = 0.f, acc1 = 0.f, acc2 = 0.f, acc3 = 0.f;
#pragma unroll
        for (int k = 0; k < 8; k++) {
            float4 a0 = areg[k][0], a1 = areg[k][1], a2 = areg[k][2], a3 = areg[k][3];
            acc0 = fmaf(av[k].x, a0.x, acc0);
            acc1 = fmaf(av[k].x, a0.y, acc1);
            acc2 = fmaf(av[k].x, a0.z, acc2);
            acc3 = fmaf(av[k].x, a0.w, acc3);
            acc0 = fmaf(av[k].y, a1.x, acc0);
            acc1 = fmaf(av[k].y, a1.y, acc1);
            acc2 = fmaf(av[k].y, a1.z, acc2);
            acc3 = fmaf(av[k].y, a1.w, acc3);
            acc0 = fmaf(av[k].z, a2.x, acc0);
            acc1 = fmaf(av[k].z, a2.y, acc1);
            acc2 = fmaf(av[k].z, a2.z, acc2);
            acc3 = fmaf(av[k].z, a2.w, acc3);
            acc0 = fmaf(av[k].w, a3.x, acc0);
            acc1 = fmaf(av[k].w, a3.y, acc1);
            acc2 = fmaf(av[k].w, a3.z, acc2);
            acc3 = fmaf(av[k].w, a3.w, acc3);
        }

        // Warp reduce (rows split across lanes).
#pragma unroll
        for (int off = 16; off > 0; off >>= 1) {
            acc0 += __shfl_xor_sync(0xffffffffu, acc0, off);
            acc1 += __shfl_xor_sync(0xffffffffu, acc1, off);
            acc2 += __shfl_xor_sync(0xffffffffu, acc2, off);
            acc3 += __shfl_xor_sync(0xffffffffu, acc3, off);
        }
        if (lane == 0) {
            red[sp][rg][cg * 4 + 0] = acc0;
            red[sp][rg][cg * 4 + 1] = acc1;
            red[sp][rg][cg * 4 + 2] = acc2;
            red[sp][rg][cg * 4 + 3] = acc3;
        }
        __syncthreads();

        // Epilogue on warp 7's lane 0 (tid 224): finalize 16 outputs, publish.
        // Warp 0 is free to start polling the next step immediately.
        if (tid == 224) {
            const float4* r0 = reinterpret_cast<const float4*>(red[sp][0]);
            const float4* r1 = reinterpret_cast<const float4*>(red[sp][1]);
            const float4* bb = reinterpret_cast<const float4*>(bjs[sp]);
            float4 v[4];
#pragma unroll
            for (int q = 0; q < 4; q++) {
                float4 a = r0[q], b = r1[q], c = bb[q];
                v[q].x = (a.x + b.x) * c.x;
                v[q].y = (a.y + b.y) * c.y;
                v[q].z = (a.z + b.z) * c.z;
                v[q].w = (a.w + b.w) * c.w;
            }
            if (s == T - 1) {
                float vs = 0.f;
#pragma unroll
                for (int q = 0; q < 4; q++) vs += v[q].x + v[q].y + v[q].z + v[q].w;
                atomicAdd(out, vs);
            } else {
                float4* dst = reinterpret_cast<float4*>(&g_alpha[sp][blk * NCOL]);
#pragma unroll
                for (int q = 0; q < 4; q++) __stcg(&dst[q], v[q]);
                st_rel(&reinterpret_cast<unsigned*>(g_flag4[sp])[blk], (unsigned)(s + 1));
            }
        }
        // No trailing barrier: red/bjs are parity double-buffered; any warp's
        // next write to this parity slot is gated by the next step's barriers,
        // which the epilogue thread only passes after its reads here.
    }
}

extern "C" void kernel_launch(void* const* d_in, const int* in_sizes, int n_in,
                              void* d_out, int out_size) {
    const int*   obs = (const int*)d_in[0];
    const float* A   = (const float*)d_in[1];
    const float* B   = (const float*)d_in[2];
    const float* pi  = (const float*)d_in[3];
    float*       out = (float*)d_out;
    (void)in_sizes; (void)n_in; (void)out_size;

    hmm_forward_kernel<<<GRID, NT>>>(obs, A, B, pi, out);
}

// round 5
// speedup vs baseline: 5.0450x; 3.4730x over previous
#include <cuda_runtime.h>

// HMM forward: alpha_t = (alpha_{t-1} @ A) * B[:, obs_t],  out = sum(alpha_{T-1})
// R5: self-validating alpha elements (value,tag) in 8B words. No flags, no
// fences, no global barrier. Per-block: 4 poller warps restripe global->SMEM,
// half-scoped and pair-scoped named barriers only. 3 rotating alpha buffers;
// epoch folded into tags for graph-replay safety.

namespace {
constexpr int GRID = 128;
constexpr int NT   = 256;
constexpr int S    = 2048;
constexpr int V    = 32768;
constexpr int T    = 4096;
constexpr int NCOL = 16;      // columns per block
}

// Each uint4 = two elements: (val0, tag0, val1, tag1). 3 rotating buffers.
__device__ uint4    g_alpha3[3][S / 2];
__device__ unsigned g_epoch = 0;
__device__ unsigned g_done  = 0;

__device__ __forceinline__ uint4 ld_vol4(const uint4* p) {
    uint4 v;
    asm volatile("ld.volatile.global.v4.u32 {%0,%1,%2,%3}, [%4];"
                 : "=r"(v.x), "=r"(v.y), "=r"(v.z), "=r"(v.w) : "l"(p) : "memory");
    return v;
}
__device__ __forceinline__ void st_cg_v2(void* p, unsigned a, unsigned b) {
    asm volatile("st.global.cg.v2.u32 [%0], {%1,%2};" :: "l"(p), "r"(a), "r"(b) : "memory");
}

__global__ void __launch_bounds__(NT, 1) hmm_forward_kernel(
    const int*   __restrict__ obs,
    const float* __restrict__ A,
    const float* __restrict__ B,
    const float* __restrict__ pi,
    float*       __restrict__ out)
{
    __shared__ __align__(16) float alpha_sm[2][2][1024]; // [parity][half][elem]
    __shared__ __align__(16) float red[2][2][NCOL];      // [parity][rowgroup][col]

    const int tid  = threadIdx.x;
    const int blk  = blockIdx.x;
    const int w    = tid >> 5;
    const int lane = tid & 31;
    const int cg   = w & 3;               // column group 0..3 (4 cols each)
    const int rg   = w >> 2;              // row group 0..1 (half = 1024 rows)
    const int jb   = blk * NCOL + cg * 4; // first of this warp's 4 columns

    // Pollers: w2,w3 -> half0 (chunks 0-7 / 8-15); w4,w5 -> half1.
    const bool is_poller = (w >= 2) && (w <= 5);
    const int  poll_half = (w <= 3) ? 0 : 1;
    const int  chunk_off = (w == 2 || w == 4) ? 0 : 8;
    // Epilogue warp per pair (cg): pair0->w0, pair1->w1, pair2->w6, pair3->w7.
    const bool is_epi = (rg == 0) ? (cg <= 1) : (cg >= 2);

    // ---- Load A tile into registers (one time) ----
    float4 areg[8][4];
#pragma unroll
    for (int k = 0; k < 8; k++) {
#pragma unroll
        for (int rr = 0; rr < 4; rr++) {
            int row = rg * 1024 + 4 * lane + 128 * k + rr;
            areg[k][rr] = *reinterpret_cast<const float4*>(&A[(size_t)row * S + jb]);
        }
    }

    const unsigned epoch = *(volatile unsigned*)&g_epoch;
    // TAG(t) strictly positive, unique across replays; zero-init never matches.
    const unsigned tagbase = epoch * 4096u + 1u;

    if (blk == 0 && tid == 0) *out = 0.0f;

    // ---- Publish alpha_0 = pi * B[:, obs[0]] with TAG(0) ----
    if (is_epi && lane < 4) {
        int   c  = jb + lane;
        int   o0 = __ldg(&obs[0]);
        float v  = pi[c] * __ldg(&B[(size_t)c * V + o0]);
        st_cg_v2(reinterpret_cast<char*>(g_alpha3[0]) + (size_t)c * 8,
                 __float_as_uint(v), tagbase);
    }

    for (int s = 1; s < T; s++) {
        const int      par  = s & 1;
        const int      bufR = (s - 1) % 3;
        const int      bufW = s % 3;
        const unsigned tagR = tagbase + (unsigned)(s - 1);
        const unsigned tagW = tagbase + (unsigned)s;

        // Epilogue lanes prefetch their emission factor (independent of alpha).
        float bj = 0.0f;
        if (is_epi && lane < 4) {
            int o = __ldg(&obs[s]);
            bj = __ldg(&B[(size_t)(jb + lane) * V + o]);
        }

        // ---- Pollers: wait for this half's 8 chunks, restripe to SMEM ----
        if (is_poller) {
            const uint4* base = &g_alpha3[bufR][poll_half * 512];
            uint4 v[8];
#pragma unroll
            for (int c = 0; c < 8; c++)
                v[c] = ld_vol4(base + (chunk_off + c) * 32 + lane);
            unsigned pend = 0xFFu;
            for (;;) {
                unsigned np = 0;
#pragma unroll
                for (int c = 0; c < 8; c++)
                    if (pend & (1u << c))
                        if (v[c].y != tagR || v[c].w != tagR) np |= 1u << c;
                if (__all_sync(0xffffffffu, np == 0u)) break;
                pend = np;
#pragma unroll
                for (int c = 0; c < 8; c++)
                    if (pend & (1u << c))
                        v[c] = ld_vol4(base + (chunk_off + c) * 32 + lane);
            }
#pragma unroll
            for (int c = 0; c < 8; c++) {
                float2 f;
                f.x = __uint_as_float(v[c].x);
                f.y = __uint_as_float(v[c].z);
                *reinterpret_cast<float2*>(
                    &alpha_sm[par][poll_half][(chunk_off + c) * 64 + 2 * lane]) = f;
            }
        }

        // Half-scoped barrier: warps 0-3 (half0) on bar 1, warps 4-7 on bar 2.
        if (rg == 0) asm volatile("bar.sync 1, 128;" ::: "memory");
        else         asm volatile("bar.sync 2, 128;" ::: "memory");

        // ---- Matvec slice: 128 FMAs per thread, A from registers ----
        const float4* sm4 = reinterpret_cast<const float4*>(alpha_sm[par][rg]);
        float acc0 = 0.f, acc1 = 0.f, acc2 = 0.f, acc3 = 0.f;
#pragma unroll
        for (int k = 0; k < 8; k++) {
            float4 av = sm4[k * 32 + lane];
            float4 a0 = areg[k][0], a1 = areg[k][1], a2 = areg[k][2], a3 = areg[k][3];
            acc0 = fmaf(av.x, a0.x, acc0);
            acc1 = fmaf(av.x, a0.y, acc1);
            acc2 = fmaf(av.x, a0.z, acc2);
            acc3 = fmaf(av.x, a0.w, acc3);
            acc0 = fmaf(av.y, a1.x, acc0);
            acc1 = fmaf(av.y, a1.y, acc1);
            acc2 = fmaf(av.y, a1.z, acc2);
            acc3 = fmaf(av.y, a1.w, acc3);
            acc0 = fmaf(av.z, a2.x, acc0);
            acc1 = fmaf(av.z, a2.y, acc1);
            acc2 = fmaf(av.z, a2.z, acc2);
            acc3 = fmaf(av.z, a2.w, acc3);
            acc0 = fmaf(av.w, a3.x, acc0);
            acc1 = fmaf(av.w, a3.y, acc1);
            acc2 = fmaf(av.w, a3.z, acc2);
            acc3 = fmaf(av.w, a3.w, acc3);
        }
#pragma unroll
        for (int off = 16; off > 0; off >>= 1) {
            acc0 += __shfl_xor_sync(0xffffffffu, acc0, off);
            acc1 += __shfl_xor_sync(0xffffffffu, acc1, off);
            acc2 += __shfl_xor_sync(0xffffffffu, acc2, off);
            acc3 += __shfl_xor_sync(0xffffffffu, acc3, off);
        }
        if (lane == 0) {
            float4 r4 = make_float4(acc0, acc1, acc2, acc3);
            *reinterpret_cast<float4*>(&red[par][rg][cg * 4]) = r4;
        }

        // Pair-scoped barrier: warps (cg, cg+4) on bar 3+cg, 64 threads.
        asm volatile("bar.sync %0, 64;" :: "r"(3 + cg) : "memory");

        // ---- Epilogue: finalize this pair's 4 columns, publish per-element ----
        if (is_epi) {
            float vv = 0.0f;
            if (lane < 4) {
                float r0 = red[par][0][cg * 4 + lane];
                float r1 = red[par][1][cg * 4 + lane];
                vv = (r0 + r1) * bj;
            }
            if (s == T - 1) {
                float t = (lane < 4) ? vv : 0.0f;
                t += __shfl_xor_sync(0xffffffffu, t, 1);
                t += __shfl_xor_sync(0xffffffffu, t, 2);
                if (lane == 0) {
                    atomicAdd(out, t);
                    unsigned d = atomicAdd(&g_done, 1u);
                    if (d == 4u * GRID - 1u) {
                        *(volatile unsigned*)&g_done  = 0u;
                        *(volatile unsigned*)&g_epoch = epoch + 1u;
                    }
                }
            } else if (lane < 4) {
                st_cg_v2(reinterpret_cast<char*>(g_alpha3[bufW]) + (size_t)(jb + lane) * 8,
                         __float_as_uint(vv), tagW);
            }
        }
        // No trailing barrier: alpha_sm/red are parity double-buffered and
        // protected by the half/pair barrier chains (writers of parity p at
        // step s+2 have passed barriers that readers at step s arrived at
        // only after completing their reads).
    }
}

extern "C" void kernel_launch(void* const* d_in, const int* in_sizes, int n_in,
                              void* d_out, int out_size) {
    const int*   obs = (const int*)d_in[0];
    const float* A   = (const float*)d_in[1];
    const float* B   = (const float*)d_in[2];
    const float* pi  = (const float*)d_in[3];
    float*       out = (float*)d_out;
    (void)in_sizes; (void)n_in; (void)out_size;

    hmm_forward_kernel<<<GRID, NT>>>(obs, A, B, pi, out);
}

// round 6
// speedup vs baseline: 5.7979x; 1.1492x over previous
#include <cuda_runtime.h>

// HMM forward: alpha_t = (alpha_{t-1} @ A) * B[:, obs_t],  out = sum(alpha_{T-1})
// R6: R5 skeleton (tagged 8B alpha elements, disjoint-line publish, no fences,
// no global barrier) + quarter-granular producer/consumer named barriers
// (bar.arrive/bar.sync) to hide producer skew under FMA, packed fp32x2 FMA,
// simplified poll loop.

namespace {
constexpr int GRID = 128;
constexpr int NT   = 256;
constexpr int S    = 2048;
constexpr int V    = 32768;
constexpr int T    = 4096;
constexpr int NCOL = 16;      // columns per block
}

typedef unsigned long long u64;

// Each uint4 = two elements: (val0, tag0, val1, tag1). 3 rotating buffers.
__device__ uint4    g_alpha3[3][S / 2];
__device__ unsigned g_epoch = 0;
__device__ unsigned g_done  = 0;

__device__ __forceinline__ uint4 ld_vol4(const uint4* p) {
    uint4 v;
    asm volatile("ld.volatile.global.v4.u32 {%0,%1,%2,%3}, [%4];"
                 : "=r"(v.x), "=r"(v.y), "=r"(v.z), "=r"(v.w) : "l"(p) : "memory");
    return v;
}
__device__ __forceinline__ void st_cg_v2(void* p, unsigned a, unsigned b) {
    asm volatile("st.global.cg.v2.u32 [%0], {%1,%2};" :: "l"(p), "r"(a), "r"(b) : "memory");
}
__device__ __forceinline__ u64 pack2(float a, float b) {
    u64 d;
    asm("mov.b64 %0, {%1,%2};" : "=l"(d) : "f"(a), "f"(b));
    return d;
}
__device__ __forceinline__ u64 fma2(u64 a, u64 b, u64 c) {
    u64 d;
    asm("fma.rn.f32x2 %0, %1, %2, %3;" : "=l"(d) : "l"(a), "l"(b), "l"(c));
    return d;
}
__device__ __forceinline__ u64 add2(u64 a, u64 b) {
    u64 d;
    asm("add.rn.f32x2 %0, %1, %2;" : "=l"(d) : "l"(a), "l"(b));
    return d;
}

__global__ void __launch_bounds__(NT, 1) hmm_forward_kernel(
    const int*   __restrict__ obs,
    const float* __restrict__ A,
    const float* __restrict__ B,
    const float* __restrict__ pi,
    float*       __restrict__ out)
{
    __shared__ __align__(16) float alpha_sm[2][2][1024]; // [parity][half][elem]
    __shared__ __align__(16) float red[2][2][NCOL];      // [parity][rowgroup][col]

    const int tid  = threadIdx.x;
    const int blk  = blockIdx.x;
    const int w    = tid >> 5;
    const int lane = tid & 31;
    const int cg   = w & 3;               // column group 0..3 (4 cols each)
    const int rg   = w >> 2;              // row group 0..1 (half = 1024 rows)
    const int jb   = blk * NCOL + cg * 4; // first of this warp's 4 columns

    // Pollers: w2 (h0 qA: chunks 0-7), w3 (h0 qB: 8-15), w4 (h1 qA), w5 (h1 qB).
    const bool is_poller = (w >= 2) && (w <= 5);
    const int  poll_half = (w <= 3) ? 0 : 1;
    const int  chunk_off = (w == 2 || w == 4) ? 0 : 8;
    const bool is_qA     = (w == 2 || w == 4);
    // Quarter barriers: half0 -> bars 1(qA),2(qB); half1 -> bars 3(qA),4(qB).
    const int  barA = 1 + rg * 2;
    const int  barB = 2 + rg * 2;
    // Epilogue warp per pair (cg): pair0->w0, pair1->w1, pair2->w6, pair3->w7.
    const bool is_epi = (rg == 0) ? (cg <= 1) : (cg >= 2);

    // ---- Load A tile into packed-pair registers (one time) ----
    // Thread covers rows rg*1024 + 4*lane + 128*k + rr (k<8, rr<4), cols jb..jb+3.
    u64 areg_lo[8][4], areg_hi[8][4];
#pragma unroll
    for (int k = 0; k < 8; k++) {
#pragma unroll
        for (int rr = 0; rr < 4; rr++) {
            int row = rg * 1024 + 4 * lane + 128 * k + rr;
            float4 a4 = *reinterpret_cast<const float4*>(&A[(size_t)row * S + jb]);
            areg_lo[k][rr] = pack2(a4.x, a4.y);
            areg_hi[k][rr] = pack2(a4.z, a4.w);
        }
    }

    const unsigned epoch = *(volatile unsigned*)&g_epoch;
    // Tags strictly positive, unique across replays; zero-init never matches.
    const unsigned tagbase = epoch * 4096u + 1u;

    if (blk == 0 && tid == 0) *out = 0.0f;

    // ---- Publish alpha_0 = pi * B[:, obs[0]] with tag(0) ----
    if (is_epi && lane < 4) {
        int   c  = jb + lane;
        int   o0 = __ldg(&obs[0]);
        float v  = pi[c] * __ldg(&B[(size_t)c * V + o0]);
        st_cg_v2(reinterpret_cast<char*>(g_alpha3[0]) + (size_t)c * 8,
                 __float_as_uint(v), tagbase);
    }

    for (int s = 1; s < T; s++) {
        const int      par  = s & 1;
        const int      bufR = (s - 1) % 3;
        const int      bufW = s % 3;
        const unsigned tagR = tagbase + (unsigned)(s - 1);
        const unsigned tagW = tagbase + (unsigned)s;

        // Epilogue lanes prefetch their emission factor (independent of alpha).
        float bj = 0.0f;
        if (is_epi && lane < 4) {
            int o = __ldg(&obs[s]);
            bj = __ldg(&B[(size_t)(jb + lane) * V + o]);
        }

        // ---- Pollers: wait for this quarter's 8 chunks, restripe to SMEM ----
        if (is_poller) {
            const uint4* base = &g_alpha3[bufR][poll_half * 512] + chunk_off * 32 + lane;
            uint4 v[8];
            for (;;) {
                bool ok = true;
#pragma unroll
                for (int c = 0; c < 8; c++) {
                    v[c] = ld_vol4(base + c * 32);
                    ok &= (v[c].y == tagR) & (v[c].w == tagR);
                }
                if (__all_sync(0xffffffffu, ok)) break;
            }
#pragma unroll
            for (int c = 0; c < 8; c++) {
                float2 f = make_float2(__uint_as_float(v[c].x), __uint_as_float(v[c].z));
                *reinterpret_cast<float2*>(
                    &alpha_sm[par][poll_half][(chunk_off + c) * 64 + 2 * lane]) = f;
            }
            // Publish my quarter to the other 3 warps of this half.
            if (is_qA) asm volatile("bar.arrive %0, 128;" :: "r"(barA) : "memory");
            else       asm volatile("bar.arrive %0, 128;" :: "r"(barB) : "memory");
        }

        const float4* sm4 = reinterpret_cast<const float4*>(alpha_sm[par][rg]);
        u64 acc01 = 0, acc23 = 0;   // packed (col0,col1), (col2,col3); 0x0 == (0.f,0.f)

        // Quarter A (k=0..3): qA poller has its data; qB poller + consumers sync.
        if (!(is_poller && is_qA))
            asm volatile("bar.sync %0, 128;" :: "r"(barA) : "memory");
#pragma unroll
        for (int k = 0; k < 4; k++) {
            float4 av = sm4[k * 32 + lane];
            u64 ax = pack2(av.x, av.x), ay = pack2(av.y, av.y);
            u64 az = pack2(av.z, av.z), aw = pack2(av.w, av.w);
            acc01 = fma2(ax, areg_lo[k][0], acc01);
            acc23 = fma2(ax, areg_hi[k][0], acc23);
            acc01 = fma2(ay, areg_lo[k][1], acc01);
            acc23 = fma2(ay, areg_hi[k][1], acc23);
            acc01 = fma2(az, areg_lo[k][2], acc01);
            acc23 = fma2(az, areg_hi[k][2], acc23);
            acc01 = fma2(aw, areg_lo[k][3], acc01);
            acc23 = fma2(aw, areg_hi[k][3], acc23);
        }
        // Quarter B (k=4..7): qB poller already has its data.
        if (!(is_poller && !is_qA))
            asm volatile("bar.sync %0, 128;" :: "r"(barB) : "memory");
#pragma unroll
        for (int k = 4; k < 8; k++) {
            float4 av = sm4[k * 32 + lane];
            u64 ax = pack2(av.x, av.x), ay = pack2(av.y, av.y);
            u64 az = pack2(av.z, av.z), aw = pack2(av.w, av.w);
            acc01 = fma2(ax, areg_lo[k][0], acc01);
            acc23 = fma2(ax, areg_hi[k][0], acc23);
            acc01 = fma2(ay, areg_lo[k][1], acc01);
            acc23 = fma2(ay, areg_hi[k][1], acc23);
            acc01 = fma2(az, areg_lo[k][2], acc01);
            acc23 = fma2(az, areg_hi[k][2], acc23);
            acc01 = fma2(aw, areg_lo[k][3], acc01);
            acc23 = fma2(aw, areg_hi[k][3], acc23);
        }

        // Warp reduce (rows split across lanes) on packed pairs.
#pragma unroll
        for (int off = 16; off > 0; off >>= 1) {
            acc01 = add2(acc01, __shfl_xor_sync(0xffffffffu, acc01, off));
            acc23 = add2(acc23, __shfl_xor_sync(0xffffffffu, acc23, off));
        }
        if (lane == 0) {
            u64* r = reinterpret_cast<u64*>(&red[par][rg][cg * 4]);
            r[0] = acc01;
            r[1] = acc23;
        }

        // Pair-scoped barrier: warps (cg, cg+4) on bar 5+cg, 64 threads.
        asm volatile("bar.sync %0, 64;" :: "r"(5 + cg) : "memory");

        // ---- Epilogue: finalize this pair's 4 columns, publish per-element ----
        if (is_epi) {
            float vv = 0.0f;
            if (lane < 4) {
                float r0 = red[par][0][cg * 4 + lane];
                float r1 = red[par][1][cg * 4 + lane];
                vv = (r0 + r1) * bj;
            }
            if (s == T - 1) {
                float t = (lane < 4) ? vv : 0.0f;
                t += __shfl_xor_sync(0xffffffffu, t, 1);
                t += __shfl_xor_sync(0xffffffffu, t, 2);
                if (lane == 0) {
                    atomicAdd(out, t);
                    unsigned d = atomicAdd(&g_done, 1u);
                    if (d == 4u * GRID - 1u) {
                        *(volatile unsigned*)&g_done  = 0u;
                        *(volatile unsigned*)&g_epoch = epoch + 1u;
                    }
                }
            } else if (lane < 4) {
                st_cg_v2(reinterpret_cast<char*>(g_alpha3[bufW]) + (size_t)(jb + lane) * 8,
                         __float_as_uint(vv), tagW);
            }
        }
        // No trailing barrier: alpha_sm/red are parity double-buffered; the
        // publish->consume->barrier chain guarantees step-s readers finish
        // before step-(s+2) writers of the same parity slot can start.
    }
}

extern "C" void kernel_launch(void* const* d_in, const int* in_sizes, int n_in,
                              void* d_out, int out_size) {
    const int*   obs = (const int*)d_in[0];
    const float* A   = (const float*)d_in[1];
    const float* B   = (const float*)d_in[2];
    const float* pi  = (const float*)d_in[3];
    float*       out = (float*)d_out;
    (void)in_sizes; (void)n_in; (void)out_size;

    hmm_forward_kernel<<<GRID, NT>>>(obs, A, B, pi, out);
}